// round 1
// baseline (speedup 1.0000x reference)
#include <cuda_runtime.h>
#include <math.h>

// ---------------------------------------------------------------------------
// Problem constants
//   B=2, T=4096, D=2048, H=16, HD=128
//   6 GEMMs of [8192x2048] @ [2048x2048] + performer-style linear attention scan
// ---------------------------------------------------------------------------
constexpr int MT = 8192;    // B*T rows
constexpr int NK = 2048;    // N and K dims of every GEMM
constexpr int HEADS = 16;
constexpr int HD = 128;
constexpr int TSEQ = 4096;
constexpr int BATCH = 2;

// OFFSET = -log(sqrt(2048)) + 1e-6
#define EXP_OFFSET (-3.8123084930796303f)

// GEMM tiling
constexpr int BM = 128, BN = 128, BK = 16;
constexpr int APAD = 20;            // As row stride (floats): conflict-free, 16B-aligned
constexpr int BPAD = 136;           // Bs row stride (floats): conflict-free, 16B-aligned
constexpr int ASZ = BM * APAD;      // floats
constexpr int BSZ = BK * BPAD;      // floats
constexpr int BUFSZ = ASZ + BSZ;    // floats per pipeline stage

// Scan tiling
constexpr int CHUNKS = 16;
constexpr int CLEN = TSEQ / CHUNKS; // 256

// ---------------------------------------------------------------------------
// Scratch (static device globals; allocation is forbidden)
// ---------------------------------------------------------------------------
__device__ float g_q [MT * NK];   // q, later reused for attn
__device__ float g_k [MT * NK];
__device__ float g_v [MT * NK];
__device__ float g_qp[MT * NK];
__device__ float g_kp[MT * NK];
__device__ float g_dot [BATCH * HEADS * TSEQ];
__device__ float g_csum[BATCH * HEADS * CHUNKS * HD];

// ---------------------------------------------------------------------------
// Small helpers
// ---------------------------------------------------------------------------
__device__ __forceinline__ void cpasync16(float* s, const float* g) {
    unsigned sa = (unsigned)__cvta_generic_to_shared(s);
    asm volatile("cp.async.cg.shared.global [%0], [%1], 16;\n" :: "r"(sa), "l"(g));
}

// Split fp32 into hi+lo tf32 pair (3xTF32 decomposition)
__device__ __forceinline__ void split_tf32(float f, unsigned& hi, unsigned& lo) {
    unsigned h;
    asm("cvt.rna.tf32.f32 %0, %1;" : "=r"(h) : "f"(f));
    float r = f - __uint_as_float(h);
    unsigned l;
    asm("cvt.rna.tf32.f32 %0, %1;" : "=r"(l) : "f"(r));
    hi = h; lo = l;
}

__device__ __forceinline__ void mma_tf32(float* d, const unsigned* a, const unsigned* b) {
    asm volatile(
        "mma.sync.aligned.m16n8k8.row.col.f32.tf32.tf32.f32 "
        "{%0,%1,%2,%3}, {%4,%5,%6,%7}, {%8,%9}, {%0,%1,%2,%3};\n"
        : "+f"(d[0]), "+f"(d[1]), "+f"(d[2]), "+f"(d[3])
        : "r"(a[0]), "r"(a[1]), "r"(a[2]), "r"(a[3]), "r"(b[0]), "r"(b[1]));
}

// ---------------------------------------------------------------------------
// GEMM: C[MT,NK] = A[MT,NK] @ B[NK,NK], optional exp(x + OFFSET) epilogue.
// 128x128 block tile, BK=16, cp.async double-buffered, 8 warps at 64x32.
// ---------------------------------------------------------------------------
__device__ __forceinline__ void load_tile(const float* __restrict__ Ab,
                                          const float* __restrict__ Bb,
                                          float* buf, int k0, int tid) {
    float* As = buf;
    float* Bs = buf + ASZ;
    // A tile: 128 rows x 16 cols = 512 float4
    #pragma unroll
    for (int p = 0; p < 2; p++) {
        int i = tid + p * 256;
        int r = i >> 2;
        int q = (i & 3) << 2;
        cpasync16(&As[r * APAD + q], Ab + (size_t)r * NK + k0 + q);
    }
    // B tile: 16 rows x 128 cols = 512 float4
    #pragma unroll
    for (int p = 0; p < 2; p++) {
        int i = tid + p * 256;
        int r = i >> 5;
        int q = (i & 31) << 2;
        cpasync16(&Bs[r * BPAD + q], Bb + (size_t)(k0 + r) * NK + q);
    }
    asm volatile("cp.async.commit_group;\n");
}

__device__ __forceinline__ void compute_tile(const float* buf, float acc[4][4][4],
                                             int wr, int wc, int g, int t) {
    const float* As = buf;
    const float* Bs = buf + ASZ;
    #pragma unroll
    for (int ks = 0; ks < 2; ks++) {
        const int kk = ks * 8;
        unsigned ah[4][4], al[4][4];
        #pragma unroll
        for (int mi = 0; mi < 4; mi++) {
            const int m0 = wr * 64 + mi * 16;
            const float* p = As + (size_t)(m0 + g) * APAD + kk + t;
            float f0 = p[0];                // a0: row g,    col t
            float f1 = p[8 * APAD];         // a1: row g+8,  col t
            float f2 = p[4];                // a2: row g,    col t+4
            float f3 = p[8 * APAD + 4];     // a3: row g+8,  col t+4
            split_tf32(f0, ah[mi][0], al[mi][0]);
            split_tf32(f1, ah[mi][1], al[mi][1]);
            split_tf32(f2, ah[mi][2], al[mi][2]);
            split_tf32(f3, ah[mi][3], al[mi][3]);
        }
        unsigned bh[4][2], bl[4][2];
        #pragma unroll
        for (int ni = 0; ni < 4; ni++) {
            const int n0 = wc * 32 + ni * 8;
            float f0 = Bs[(kk + t) * BPAD + n0 + g];       // b0: k=t,   n=g
            float f1 = Bs[(kk + t + 4) * BPAD + n0 + g];   // b1: k=t+4, n=g
            split_tf32(f0, bh[ni][0], bl[ni][0]);
            split_tf32(f1, bh[ni][1], bl[ni][1]);
        }
        #pragma unroll
        for (int mi = 0; mi < 4; mi++) {
            #pragma unroll
            for (int ni = 0; ni < 4; ni++) {
                mma_tf32(acc[mi][ni], ah[mi], bh[ni]);
                mma_tf32(acc[mi][ni], ah[mi], bl[ni]);
                mma_tf32(acc[mi][ni], al[mi], bh[ni]);
            }
        }
    }
}

template <bool EXP>
__global__ void __launch_bounds__(256, 1)
gemm3t_kernel(const float* __restrict__ A, const float* __restrict__ B,
              float* __restrict__ C) {
    __shared__ float sm[2 * BUFSZ];
    const int tid = threadIdx.x;
    const int lane = tid & 31;
    const int wid = tid >> 5;
    const int wr = wid >> 2;    // 0..1  (M direction)
    const int wc = wid & 3;     // 0..3  (N direction)
    const int g = lane >> 2;    // 0..7
    const int t = lane & 3;     // 0..3
    const int bm = blockIdx.y * BM;
    const int bn = blockIdx.x * BN;
    const float* Ab = A + (size_t)bm * NK;
    const float* Bb = B + bn;

    float acc[4][4][4];
    #pragma unroll
    for (int mi = 0; mi < 4; mi++)
        #pragma unroll
        for (int ni = 0; ni < 4; ni++)
            #pragma unroll
            for (int r = 0; r < 4; r++)
                acc[mi][ni][r] = 0.0f;

    load_tile(Ab, Bb, sm, 0, tid);
    constexpr int NT = NK / BK;  // 128
    #pragma unroll 1
    for (int kt = 0; kt < NT; kt++) {
        if (kt + 1 < NT) {
            load_tile(Ab, Bb, sm + ((kt + 1) & 1) * BUFSZ, (kt + 1) * BK, tid);
            asm volatile("cp.async.wait_group 1;\n");
        } else {
            asm volatile("cp.async.wait_group 0;\n");
        }
        __syncthreads();
        compute_tile(sm + (kt & 1) * BUFSZ, acc, wr, wc, g, t);
        __syncthreads();
    }

    // Epilogue
    float* Cb = C + (size_t)bm * NK + bn;
    #pragma unroll
    for (int mi = 0; mi < 4; mi++) {
        const int r0 = wr * 64 + mi * 16 + g;
        #pragma unroll
        for (int ni = 0; ni < 4; ni++) {
            const int c0 = wc * 32 + ni * 8 + 2 * t;
            float v0 = acc[mi][ni][0], v1 = acc[mi][ni][1];
            float v2 = acc[mi][ni][2], v3 = acc[mi][ni][3];
            if (EXP) {
                v0 = expf(v0 + EXP_OFFSET);
                v1 = expf(v1 + EXP_OFFSET);
                v2 = expf(v2 + EXP_OFFSET);
                v3 = expf(v3 + EXP_OFFSET);
            }
            *(float2*)&Cb[(size_t)r0 * NK + c0]       = make_float2(v0, v1);
            *(float2*)&Cb[(size_t)(r0 + 8) * NK + c0] = make_float2(v2, v3);
        }
    }
}

// ---------------------------------------------------------------------------
// dot[b,h,t] = sum_d qp[b,t,h*128+d] * kp[b,t,h*128+d]
// One block per (b,t) row; 256 threads, 8 floats each; 16-lane segment reduce.
// ---------------------------------------------------------------------------
__global__ void dot_kernel(const float* __restrict__ qp, const float* __restrict__ kp,
                           float* __restrict__ dotv) {
    const int row = blockIdx.x;           // b*T + t
    const int tid = threadIdx.x;          // 0..255
    const float4* q4 = (const float4*)(qp + (size_t)row * NK);
    const float4* k4 = (const float4*)(kp + (size_t)row * NK);
    const int base = tid * 2;
    float4 a = q4[base], b = k4[base];
    float s = a.x * b.x + a.y * b.y + a.z * b.z + a.w * b.w;
    a = q4[base + 1]; b = k4[base + 1];
    s += a.x * b.x + a.y * b.y + a.z * b.z + a.w * b.w;
    #pragma unroll
    for (int off = 8; off >= 1; off >>= 1)
        s += __shfl_down_sync(0xffffffffu, s, off, 16);
    if ((tid & 15) == 0) {
        const int h = tid >> 4;
        const int bb = row >> 12;
        const int t = row & (TSEQ - 1);
        dotv[((size_t)bb * HEADS + h) * TSEQ + t] = s;
    }
}

// ---------------------------------------------------------------------------
// Chunked scan, phase 1: per-chunk sums of dot[t]*v[t,d]
// grid = B*H*CHUNKS (512), block = 128 (one thread per d)
// ---------------------------------------------------------------------------
__global__ void scan1_kernel(const float* __restrict__ dotv, const float* __restrict__ v,
                             float* __restrict__ csum) {
    const int bid = blockIdx.x;
    const int c = bid & (CHUNKS - 1);
    const int bh = bid >> 4;              // b*16 + h
    const int h = bh & (HEADS - 1);
    const int b = bh >> 4;
    const int d = threadIdx.x;
    const float* dptr = dotv + (size_t)bh * TSEQ + c * CLEN;
    const float* vp = v + ((size_t)(b * TSEQ + c * CLEN)) * NK + h * HD + d;
    float s = 0.0f;
    #pragma unroll 8
    for (int i = 0; i < CLEN; i++)
        s = fmaf(dptr[i], vp[(size_t)i * NK], s);
    csum[(size_t)bid * HD + d] = s;
}

// ---------------------------------------------------------------------------
// Chunked scan, phase 2: offset = scan of chunk sums; local inclusive cumsum;
// divide by kp; write attn in [B,T,D] layout.
// ---------------------------------------------------------------------------
__global__ void scan2_kernel(const float* __restrict__ dotv, const float* __restrict__ v,
                             const float* __restrict__ kp, const float* __restrict__ csum,
                             float* __restrict__ attn) {
    const int bid = blockIdx.x;
    const int c = bid & (CHUNKS - 1);
    const int bh = bid >> 4;
    const int h = bh & (HEADS - 1);
    const int b = bh >> 4;
    const int d = threadIdx.x;

    float run = 0.0f;
    for (int c2 = 0; c2 < c; c2++)
        run += csum[((size_t)bh * CHUNKS + c2) * HD + d];

    const float* dptr = dotv + (size_t)bh * TSEQ + c * CLEN;
    const size_t off = ((size_t)(b * TSEQ + c * CLEN)) * NK + h * HD + d;
    const float* vp = v + off;
    const float* kpp = kp + off;
    float* ap = attn + off;
    #pragma unroll 4
    for (int i = 0; i < CLEN; i++) {
        run = fmaf(dptr[i], vp[(size_t)i * NK], run);
        ap[(size_t)i * NK] = run / kpp[(size_t)i * NK];
    }
}

// ---------------------------------------------------------------------------
// Launch: 6 GEMMs + dot + 2-phase scan, all on the default stream (graph order)
// ---------------------------------------------------------------------------
extern "C" void kernel_launch(void* const* d_in, const int* in_sizes, int n_in,
                              void* d_out, int out_size) {
    (void)in_sizes; (void)n_in; (void)out_size;
    const float* hs = (const float*)d_in[0];
    const float* Wq = (const float*)d_in[1];
    const float* Wk = (const float*)d_in[2];
    const float* Wv = (const float*)d_in[3];
    const float* Wo = (const float*)d_in[4];
    const float* Fq = (const float*)d_in[5];
    const float* Fk = (const float*)d_in[6];
    float* out = (float*)d_out;

    float *q, *k, *v, *qp, *kp, *dotv, *csum;
    cudaGetSymbolAddress((void**)&q,    g_q);
    cudaGetSymbolAddress((void**)&k,    g_k);
    cudaGetSymbolAddress((void**)&v,    g_v);
    cudaGetSymbolAddress((void**)&qp,   g_qp);
    cudaGetSymbolAddress((void**)&kp,   g_kp);
    cudaGetSymbolAddress((void**)&dotv, g_dot);
    cudaGetSymbolAddress((void**)&csum, g_csum);

    dim3 ggrid(NK / BN, MT / BM);   // (16, 64)
    dim3 gblk(256);

    gemm3t_kernel<false><<<ggrid, gblk>>>(hs, Wq, q);
    gemm3t_kernel<false><<<ggrid, gblk>>>(hs, Wk, k);
    gemm3t_kernel<false><<<ggrid, gblk>>>(hs, Wv, v);
    gemm3t_kernel<true ><<<ggrid, gblk>>>(q,  Fq, qp);
    gemm3t_kernel<true ><<<ggrid, gblk>>>(k,  Fk, kp);

    dot_kernel<<<MT, 256>>>(qp, kp, dotv);
    scan1_kernel<<<BATCH * HEADS * CHUNKS, HD>>>(dotv, v, csum);
    // attn reuses g_q (q is dead after qp is computed)
    scan2_kernel<<<BATCH * HEADS * CHUNKS, HD>>>(dotv, v, kp, csum, q);

    gemm3t_kernel<false><<<ggrid, gblk>>>(q, Wo, out);
}